// round 12
// baseline (speedup 1.0000x reference)
#include <cuda_runtime.h>
#include <cuda_bf16.h>
#include <cstdint>

#define LL 65536
#define DD 256
#define CC 1024     // number of chunks
#define RR 64       // rows per chunk
#define NSEG 32     // segments
#define SEGC 32     // chunks per segment (CC / NSEG)

#define NEG_INF __int_as_float(0xff800000)

// ---- scratch (device globals) ----
__device__ float g_s[LL];            // s[i] = K[i]·q
__device__ float g_M[CC], g_U[CC];   // per-chunk aggregates (U ref M)
__device__ float g_W[CC * DD];       // per-chunk vector aggregate (ref M_c)
__device__ float g_Mp[CC], g_Up[CC]; // exclusive prefix (Up ref Mp)
__device__ float g_Wp[CC * DD];      // segment-local exclusive W prefix (ref Mp_c)
__device__ float g_seg[NSEG * DD];   // segment aggregates (ref Mp[(b+1)*SEGC])

// evict-last L2 policy (created once per thread; uniform)
__device__ __forceinline__ uint64_t mk_evict_last_policy() {
    uint64_t pol;
    asm("createpolicy.fractional.L2::evict_last.b64 %0, 1.0;" : "=l"(pol));
    return pol;
}
// V loads in pass1: keep in L2 (evict-last) so pass2 re-reads hit L2.
__device__ __forceinline__ float4 ldg_el(const float4* p, uint64_t pol) {
    float4 v;
    asm("ld.global.L2::cache_hint.v4.f32 {%0,%1,%2,%3}, [%4], %5;"
        : "=f"(v.x), "=f"(v.y), "=f"(v.z), "=f"(v.w) : "l"(p), "l"(pol));
    return v;
}

// ============================================================
// Pass 1: s = K·q ; per-chunk (M, U, W) reduction.
// K: evict-first (streamed once). V: evict-last (L2-pinned for pass2).
// ============================================================
__global__ __launch_bounds__(256, 8) void k_pass1(const float* __restrict__ K,
                                                  const float* __restrict__ V,
                                                  const float* __restrict__ q) {
    __shared__ __align__(16) float q_sh[DD];
    __shared__ __align__(16) float wpart[4][DD];
    __shared__ float s_sh[RR];
    __shared__ float e_sh[RR];

    const int c = blockIdx.x;
    const int t = threadIdx.x;
    const int lane = t & 31;
    const int wid = t >> 5;

    const uint64_t pol = mk_evict_last_policy();

    q_sh[t] = q[t];
    __syncthreads();

    const float4* q4 = reinterpret_cast<const float4*>(q_sh);
    const float4* K4 = reinterpret_cast<const float4*>(K) + (size_t)c * RR * 64;

    // --- K-dot: 8 warps x 8 rows, one warp per row ---
    float4 qa = q4[lane], qb = q4[32 + lane];
#pragma unroll
    for (int k = 0; k < RR / 8; k++) {
        int r = wid * (RR / 8) + k;
        float4 ka = __ldcs(&K4[r * 64 + lane]);        // K read-once: evict-first
        float4 kb = __ldcs(&K4[r * 64 + 32 + lane]);
        float p = ka.x * qa.x + ka.y * qa.y + ka.z * qa.z + ka.w * qa.w
                + kb.x * qb.x + kb.y * qb.y + kb.z * qb.z + kb.w * qb.w;
#pragma unroll
        for (int o = 16; o; o >>= 1) p += __shfl_xor_sync(0xffffffffu, p, o);
        if (lane == 0) s_sh[r] = p;
    }
    __syncthreads();

    // --- prefetch first 4 V rows per thread (independent of reduction) ---
    const int grp = t >> 6;
    const int j = t & 63;
    const float4* V4 = reinterpret_cast<const float4*>(V) + (size_t)c * RR * 64;
    float4 v0 = ldg_el(&V4[(grp +  0) * 64 + j], pol);
    float4 v1 = ldg_el(&V4[(grp +  4) * 64 + j], pol);
    float4 v2 = ldg_el(&V4[(grp +  8) * 64 + j], pol);
    float4 v3 = ldg_el(&V4[(grp + 12) * 64 + j], pol);

    // --- warp 0: M, e, U (64 expf total) ---
    if (wid == 0) {
        float s0 = s_sh[lane], s1 = s_sh[32 + lane];
        float m = fmaxf(s0, s1);
#pragma unroll
        for (int o = 16; o; o >>= 1) m = fmaxf(m, __shfl_xor_sync(0xffffffffu, m, o));
        float e0 = __expf(s0 - m), e1 = __expf(s1 - m);
        e_sh[lane] = e0; e_sh[32 + lane] = e1;
        float u = e0 + e1;
#pragma unroll
        for (int o = 16; o; o >>= 1) u += __shfl_xor_sync(0xffffffffu, u, o);
        if (lane == 0) { g_M[c] = m; g_U[c] = u; }
    }
    if (t < RR) g_s[c * RR + t] = s_sh[t];
    __syncthreads();

    // --- V accumulate: consume prefetched batch, then stream the rest ---
    float4 acc;
    {
        float e0 = e_sh[grp], e1 = e_sh[grp + 4], e2 = e_sh[grp + 8], e3 = e_sh[grp + 12];
        acc.x = e0 * v0.x + e1 * v1.x + e2 * v2.x + e3 * v3.x;
        acc.y = e0 * v0.y + e1 * v1.y + e2 * v2.y + e3 * v3.y;
        acc.z = e0 * v0.z + e1 * v1.z + e2 * v2.z + e3 * v3.z;
        acc.w = e0 * v0.w + e1 * v1.w + e2 * v2.w + e3 * v3.w;
    }
#pragma unroll
    for (int i = grp + 16; i < RR; i += 4) {
        float e = e_sh[i];
        float4 v = ldg_el(&V4[i * 64 + j], pol);
        acc.x = fmaf(e, v.x, acc.x); acc.y = fmaf(e, v.y, acc.y);
        acc.z = fmaf(e, v.z, acc.z); acc.w = fmaf(e, v.w, acc.w);
    }
    reinterpret_cast<float4*>(wpart[grp])[j] = acc;
    __syncthreads();
    g_W[(size_t)c * DD + t] = wpart[0][t] + wpart[1][t] + wpart[2][t] + wpart[3][t];
}

// ============================================================
// Mid kernel: NSEG blocks. All-parallel scalar scans; block b
// does the register-resident segment W-scan for its chunks.
// ============================================================
__global__ __launch_bounds__(256) void k_mid() {
    __shared__ float Pm[CC];
    __shared__ float alsh[CC];
    __shared__ float gash[CC];
    __shared__ float As[CC];
    __shared__ float Bs[CC];

    const int b = blockIdx.x;
    const int t = threadIdx.x;

    float mv[4];
#pragma unroll
    for (int r = 0; r < 4; r++) {
        mv[r] = g_M[t + r * 256];
        Pm[t + r * 256] = mv[r];
    }
    __syncthreads();

    // inclusive prefix max (Hillis-Steele), 4 elems/thread
    float cm[4];
#pragma unroll
    for (int r = 0; r < 4; r++) cm[r] = mv[r];
    for (int off = 1; off < CC; off <<= 1) {
        float v[4];
#pragma unroll
        for (int r = 0; r < 4; r++) {
            int i = t + r * 256;
            v[r] = (i >= off) ? Pm[i - off] : NEG_INF;
        }
        __syncthreads();
#pragma unroll
        for (int r = 0; r < 4; r++) {
            cm[r] = fmaxf(cm[r], v[r]);
            Pm[t + r * 256] = cm[r];
        }
        __syncthreads();
    }

    float ca[4], cb[4];
#pragma unroll
    for (int r = 0; r < 4; r++) {
        int i = t + r * 256;
        float Minc = Pm[i];
        float Mp = (i == 0) ? NEG_INF : Pm[i - 1];
        float a = (i == 0) ? 0.f : __expf(Mp - Minc);
        float g = __expf(mv[r] - Minc);
        alsh[i] = a;
        gash[i] = g;
        ca[r] = a;
        cb[r] = g_U[i] * g;
        As[i] = ca[r];
        Bs[i] = cb[r];
        if (b == 0) g_Mp[i] = Mp;
    }
    __syncthreads();

    // inclusive pair scan for u
    for (int off = 1; off < CC; off <<= 1) {
        float va[4], vb[4];
#pragma unroll
        for (int r = 0; r < 4; r++) {
            int i = t + r * 256;
            if (i >= off) { va[r] = As[i - off]; vb[r] = Bs[i - off]; }
            else          { va[r] = 1.f;         vb[r] = 0.f; }
        }
        __syncthreads();
#pragma unroll
        for (int r = 0; r < 4; r++) {
            int i = t + r * 256;
            cb[r] = fmaf(vb[r], ca[r], cb[r]);
            ca[r] = va[r] * ca[r];
            As[i] = ca[r];
            Bs[i] = cb[r];
        }
        __syncthreads();
    }

    if (b == 0) {
#pragma unroll
        for (int r = 0; r < 4; r++) {
            int i = t + r * 256;
            g_Up[i] = (i == 0) ? 0.f : Bs[i - 1];   // exclusive, ref Mp_i
        }
    }

    // segment W-scan, register-resident
    const int j0 = b * SEGC;
    const float* Wsrc = g_W + (size_t)j0 * DD + t;
    float* Wdst = g_Wp + (size_t)j0 * DD + t;

    float wc[SEGC];
#pragma unroll
    for (int j = 0; j < SEGC; j++) wc[j] = Wsrc[(size_t)j * DD];

    float w = 0.f;
#pragma unroll
    for (int j = 0; j < SEGC; j++) {
        Wdst[(size_t)j * DD] = w;              // exclusive within segment, ref Mp_c
        w = fmaf(w, alsh[j0 + j], wc[j] * gash[j0 + j]);
    }
    g_seg[b * DD + t] = w;                     // ref Mp[(b+1)*SEGC]
}

// ============================================================
// Pass 2: per-row recurrence, stream V -> out.
// V is L2-resident (evict-last in pass1); read it with __ldcs
// (evict-first) to free L2 progressively. Reverse chunk order.
// ============================================================
__global__ __launch_bounds__(256, 8) void k_pass2(const float* __restrict__ V,
                                                  float* __restrict__ out) {
    __shared__ float s_loc[RR], m_sh[RR];
    __shared__ float a_sh[RR], b_sh[RR];
    __shared__ float sA[RR], sB[RR];
    __shared__ float inv_sh[RR];
    __shared__ float fac_sh[NSEG];

    const int c = (CC - 1) - blockIdx.x;
    const int t = threadIdx.x;

    const float* Vb = V + (size_t)c * RR * DD + t;
    float* Ob = out + (size_t)c * RR * DD + t;

    // --- V prefetch at entry: independent of everything below ---
    float cur[8];
#pragma unroll
    for (int j = 0; j < 8; j++) cur[j] = __ldcs(&Vb[(size_t)j * DD]);

    const float Mp_c = g_Mp[c];
    const float Up_c = g_Up[c];
    const int seg = c / SEGC;

    if (t < RR) {
        float sv = g_s[c * RR + t];
        s_loc[t] = sv;
        m_sh[t] = sv;
    }
    // telescoped carry factors: fac[sb] = exp(Mp[(sb+1)*SEGC] - Mp_c), sb < seg
    if (t < seg) fac_sh[t] = __expf(g_Mp[(t + 1) * SEGC] - Mp_c);
    __syncthreads();

    // seed: w = Wp_c + sum_sb g_seg[sb][t] * fac[sb]  (independent loads)
    float w = g_Wp[(size_t)c * DD + t];
#pragma unroll 4
    for (int sb = 0; sb < seg; sb++)
        w = fmaf(__ldcg(&g_seg[sb * DD + t]), fac_sh[sb], w);

    // inclusive prefix max over s within the chunk
    float cmx = (t < RR) ? m_sh[t] : NEG_INF;
#pragma unroll
    for (int off = 1; off < RR; off <<= 1) {
        float v = NEG_INF;
        if (t < RR && t >= off) v = m_sh[t - off];
        __syncthreads();
        if (t < RR) { cmx = fmaxf(cmx, v); m_sh[t] = cmx; }
        __syncthreads();
    }

    float cA = 1.f, cB = 0.f;
    if (t < RR) {
        float mi = fmaxf(m_sh[t], Mp_c);
        float mp = (t == 0) ? Mp_c : fmaxf(m_sh[t - 1], Mp_c);
        float a = __expf(mp - mi);            // exp(-inf - finite) = 0 : safe
        float bb = __expf(s_loc[t] - mi);
        a_sh[t] = a;
        b_sh[t] = bb;
        cA = a; cB = bb;
        sA[t] = a; sB[t] = bb;
    }
    __syncthreads();

    // inclusive pair scan: u_i = B_i + A_i * Up_c
#pragma unroll
    for (int off = 1; off < RR; off <<= 1) {
        float va = 1.f, vb = 0.f;
        if (t < RR && t >= off) { va = sA[t - off]; vb = sB[t - off]; }
        __syncthreads();
        if (t < RR) {
            cB = fmaf(vb, cA, cB);
            cA = va * cA;
            sA[t] = cA; sB[t] = cB;
        }
        __syncthreads();
    }
    if (t < RR) inv_sh[t] = 1.0f / fmaf(cA, Up_c, cB);
    __syncthreads();

    // --- stream: w recurrence over 64 rows, double-buffered ---
    for (int ib = 0; ib < RR; ib += 8) {
        float nxt[8];
#pragma unroll
        for (int j = 0; j < 8; j++)
            nxt[j] = (ib + 8 < RR) ? __ldcs(&Vb[(size_t)(ib + 8 + j) * DD]) : 0.f;
#pragma unroll
        for (int j = 0; j < 8; j++) {
            int i = ib + j;
            w = fmaf(w, a_sh[i], b_sh[i] * cur[j]);
            __stcs(&Ob[(size_t)i * DD], w * inv_sh[i]);   // write-once: stream
        }
#pragma unroll
        for (int j = 0; j < 8; j++) cur[j] = nxt[j];
    }
}

// ============================================================
extern "C" void kernel_launch(void* const* d_in, const int* in_sizes, int n_in,
                              void* d_out, int out_size) {
    const float* K = (const float*)d_in[0];
    const float* V = (const float*)d_in[1];
    const float* q = (const float*)d_in[2];
    float* out = (float*)d_out;

    k_pass1<<<CC, 256>>>(K, V, q);
    k_mid<<<NSEG, 256>>>();
    k_pass2<<<CC, 256>>>(V, out);
}

// round 13
// speedup vs baseline: 1.0827x; 1.0827x over previous
#include <cuda_runtime.h>
#include <cuda_bf16.h>
#include <cstdint>

#define LL 65536
#define DD 256
#define CC 1024     // number of chunks
#define RR 64       // rows per chunk
#define NSEG 32     // segments
#define SEGC 32     // chunks per segment (CC / NSEG)

#define NEG_INF __int_as_float(0xff800000)

// ---- scratch (device globals) ----
__device__ float g_s[LL];            // s[i] = K[i]·q
__device__ float g_M[CC], g_U[CC];   // per-chunk aggregates (U ref M)
__device__ float g_W[CC * DD];       // per-chunk vector aggregate (ref M_c)
__device__ float g_Mp[CC], g_Up[CC]; // exclusive prefix (Up ref Mp)
__device__ float g_Wp[CC * DD];      // segment-local exclusive W prefix (ref Mp_c)
__device__ float g_seg[NSEG * DD];   // segment aggregates (ref Mp[(b+1)*SEGC])

__device__ __forceinline__ void pdl_trigger() {
    asm volatile("griddepcontrol.launch_dependents;");
}
__device__ __forceinline__ void pdl_wait() {
    asm volatile("griddepcontrol.wait;");
}

// ============================================================
// Pass 1: s = K·q ; per-chunk (M, U, W) reduction.
// ============================================================
__global__ __launch_bounds__(256, 8) void k_pass1(const float* __restrict__ K,
                                                  const float* __restrict__ V,
                                                  const float* __restrict__ q) {
    __shared__ __align__(16) float q_sh[DD];
    __shared__ __align__(16) float wpart[4][DD];
    __shared__ float s_sh[RR];
    __shared__ float e_sh[RR];

    const int c = blockIdx.x;
    const int t = threadIdx.x;
    const int lane = t & 31;
    const int wid = t >> 5;

    q_sh[t] = q[t];
    __syncthreads();

    const float4* q4 = reinterpret_cast<const float4*>(q_sh);
    const float4* K4 = reinterpret_cast<const float4*>(K) + (size_t)c * RR * 64;

    // --- K-dot: 8 warps x 8 rows, one warp per row ---
    float4 qa = q4[lane], qb = q4[32 + lane];
#pragma unroll
    for (int k = 0; k < RR / 8; k++) {
        int r = wid * (RR / 8) + k;
        float4 ka = __ldcs(&K4[r * 64 + lane]);        // K read-once: evict-first
        float4 kb = __ldcs(&K4[r * 64 + 32 + lane]);
        float p = ka.x * qa.x + ka.y * qa.y + ka.z * qa.z + ka.w * qa.w
                + kb.x * qb.x + kb.y * qb.y + kb.z * qb.z + kb.w * qb.w;
#pragma unroll
        for (int o = 16; o; o >>= 1) p += __shfl_xor_sync(0xffffffffu, p, o);
        if (lane == 0) s_sh[r] = p;
    }
    __syncthreads();

    // --- prefetch first 4 V rows per thread (independent of reduction) ---
    const int grp = t >> 6;
    const int j = t & 63;
    const float4* V4 = reinterpret_cast<const float4*>(V) + (size_t)c * RR * 64;
    float4 v0 = V4[(grp +  0) * 64 + j];
    float4 v1 = V4[(grp +  4) * 64 + j];
    float4 v2 = V4[(grp +  8) * 64 + j];
    float4 v3 = V4[(grp + 12) * 64 + j];

    // --- warp 0: M, e, U (64 expf total) ---
    if (wid == 0) {
        float s0 = s_sh[lane], s1 = s_sh[32 + lane];
        float m = fmaxf(s0, s1);
#pragma unroll
        for (int o = 16; o; o >>= 1) m = fmaxf(m, __shfl_xor_sync(0xffffffffu, m, o));
        float e0 = __expf(s0 - m), e1 = __expf(s1 - m);
        e_sh[lane] = e0; e_sh[32 + lane] = e1;
        float u = e0 + e1;
#pragma unroll
        for (int o = 16; o; o >>= 1) u += __shfl_xor_sync(0xffffffffu, u, o);
        if (lane == 0) { g_M[c] = m; g_U[c] = u; }
    }
    if (t < RR) g_s[c * RR + t] = s_sh[t];
    __syncthreads();

    // --- V accumulate: consume prefetched batch, then stream the rest ---
    float4 acc;
    {
        float e0 = e_sh[grp], e1 = e_sh[grp + 4], e2 = e_sh[grp + 8], e3 = e_sh[grp + 12];
        acc.x = e0 * v0.x + e1 * v1.x + e2 * v2.x + e3 * v3.x;
        acc.y = e0 * v0.y + e1 * v1.y + e2 * v2.y + e3 * v3.y;
        acc.z = e0 * v0.z + e1 * v1.z + e2 * v2.z + e3 * v3.z;
        acc.w = e0 * v0.w + e1 * v1.w + e2 * v2.w + e3 * v3.w;
    }
#pragma unroll
    for (int i = grp + 16; i < RR; i += 4) {
        float e = e_sh[i];
        float4 v = V4[i * 64 + j];
        acc.x = fmaf(e, v.x, acc.x); acc.y = fmaf(e, v.y, acc.y);
        acc.z = fmaf(e, v.z, acc.z); acc.w = fmaf(e, v.w, acc.w);
    }
    reinterpret_cast<float4*>(wpart[grp])[j] = acc;
    __syncthreads();
    g_W[(size_t)c * DD + t] = wpart[0][t] + wpart[1][t] + wpart[2][t] + wpart[3][t];

    pdl_trigger();   // all writes issued; let k_mid launch
}

// ============================================================
// Mid kernel: NSEG blocks. All-parallel scalar scans; block b
// does the register-resident segment W-scan for its chunks.
// ============================================================
__global__ __launch_bounds__(256) void k_mid() {
    __shared__ float Pm[CC];
    __shared__ float alsh[CC];
    __shared__ float gash[CC];
    __shared__ float As[CC];
    __shared__ float Bs[CC];

    const int b = blockIdx.x;
    const int t = threadIdx.x;

    pdl_wait();      // need pass1's g_M/g_U/g_W/g_s

    float mv[4];
#pragma unroll
    for (int r = 0; r < 4; r++) {
        mv[r] = g_M[t + r * 256];
        Pm[t + r * 256] = mv[r];
    }
    __syncthreads();

    // inclusive prefix max (Hillis-Steele), 4 elems/thread
    float cm[4];
#pragma unroll
    for (int r = 0; r < 4; r++) cm[r] = mv[r];
    for (int off = 1; off < CC; off <<= 1) {
        float v[4];
#pragma unroll
        for (int r = 0; r < 4; r++) {
            int i = t + r * 256;
            v[r] = (i >= off) ? Pm[i - off] : NEG_INF;
        }
        __syncthreads();
#pragma unroll
        for (int r = 0; r < 4; r++) {
            cm[r] = fmaxf(cm[r], v[r]);
            Pm[t + r * 256] = cm[r];
        }
        __syncthreads();
    }

    float ca[4], cb[4];
#pragma unroll
    for (int r = 0; r < 4; r++) {
        int i = t + r * 256;
        float Minc = Pm[i];
        float Mp = (i == 0) ? NEG_INF : Pm[i - 1];
        float a = (i == 0) ? 0.f : __expf(Mp - Minc);
        float g = __expf(mv[r] - Minc);
        alsh[i] = a;
        gash[i] = g;
        ca[r] = a;
        cb[r] = g_U[i] * g;
        As[i] = ca[r];
        Bs[i] = cb[r];
        if (b == 0) g_Mp[i] = Mp;
    }
    __syncthreads();

    // inclusive pair scan for u
    for (int off = 1; off < CC; off <<= 1) {
        float va[4], vb[4];
#pragma unroll
        for (int r = 0; r < 4; r++) {
            int i = t + r * 256;
            if (i >= off) { va[r] = As[i - off]; vb[r] = Bs[i - off]; }
            else          { va[r] = 1.f;         vb[r] = 0.f; }
        }
        __syncthreads();
#pragma unroll
        for (int r = 0; r < 4; r++) {
            int i = t + r * 256;
            cb[r] = fmaf(vb[r], ca[r], cb[r]);
            ca[r] = va[r] * ca[r];
            As[i] = ca[r];
            Bs[i] = cb[r];
        }
        __syncthreads();
    }

    if (b == 0) {
#pragma unroll
        for (int r = 0; r < 4; r++) {
            int i = t + r * 256;
            g_Up[i] = (i == 0) ? 0.f : Bs[i - 1];   // exclusive, ref Mp_i
        }
    }

    // segment W-scan, register-resident
    const int j0 = b * SEGC;
    const float* Wsrc = g_W + (size_t)j0 * DD + t;
    float* Wdst = g_Wp + (size_t)j0 * DD + t;

    float wc[SEGC];
#pragma unroll
    for (int j = 0; j < SEGC; j++) wc[j] = Wsrc[(size_t)j * DD];

    float w = 0.f;
#pragma unroll
    for (int j = 0; j < SEGC; j++) {
        Wdst[(size_t)j * DD] = w;              // exclusive within segment, ref Mp_c
        w = fmaf(w, alsh[j0 + j], wc[j] * gash[j0 + j]);
    }
    g_seg[b * DD + t] = w;                     // ref Mp[(b+1)*SEGC]

    pdl_trigger();   // all writes issued; let k_pass2 launch
}

// ============================================================
// Pass 2: per-row recurrence, stream V -> out.
// V cur[8] loaded BEFORE the PDL wait (V untouched by mid) so
// the first DRAM batch overlaps mid's tail + our preamble.
// ============================================================
__global__ __launch_bounds__(256, 8) void k_pass2(const float* __restrict__ V,
                                                  float* __restrict__ out) {
    __shared__ float s_loc[RR], m_sh[RR];
    __shared__ float a_sh[RR], b_sh[RR];
    __shared__ float sA[RR], sB[RR];
    __shared__ float inv_sh[RR];
    __shared__ float fac_sh[NSEG];

    const int c = (CC - 1) - blockIdx.x;
    const int t = threadIdx.x;

    const float* Vb = V + (size_t)c * RR * DD + t;
    float* Ob = out + (size_t)c * RR * DD + t;

    // --- V prefetch BEFORE wait: input data, independent of mid ---
    float cur[8];
#pragma unroll
    for (int j = 0; j < 8; j++) cur[j] = Vb[(size_t)j * DD];

    pdl_wait();      // need mid's g_Mp/g_Up/g_Wp/g_seg (and pass1's g_s)

    const float Mp_c = g_Mp[c];
    const float Up_c = g_Up[c];
    const int seg = c / SEGC;

    if (t < RR) {
        float sv = g_s[c * RR + t];
        s_loc[t] = sv;
        m_sh[t] = sv;
    }
    // telescoped carry factors: fac[sb] = exp(Mp[(sb+1)*SEGC] - Mp_c), sb < seg
    if (t < seg) fac_sh[t] = __expf(g_Mp[(t + 1) * SEGC] - Mp_c);
    __syncthreads();

    // seed: w = Wp_c + sum_sb g_seg[sb][t] * fac[sb]  (independent loads)
    float w = g_Wp[(size_t)c * DD + t];
#pragma unroll 4
    for (int sb = 0; sb < seg; sb++)
        w = fmaf(__ldcg(&g_seg[sb * DD + t]), fac_sh[sb], w);

    // inclusive prefix max over s within the chunk
    float cmx = (t < RR) ? m_sh[t] : NEG_INF;
#pragma unroll
    for (int off = 1; off < RR; off <<= 1) {
        float v = NEG_INF;
        if (t < RR && t >= off) v = m_sh[t - off];
        __syncthreads();
        if (t < RR) { cmx = fmaxf(cmx, v); m_sh[t] = cmx; }
        __syncthreads();
    }

    float cA = 1.f, cB = 0.f;
    if (t < RR) {
        float mi = fmaxf(m_sh[t], Mp_c);
        float mp = (t == 0) ? Mp_c : fmaxf(m_sh[t - 1], Mp_c);
        float a = __expf(mp - mi);            // exp(-inf - finite) = 0 : safe
        float bb = __expf(s_loc[t] - mi);
        a_sh[t] = a;
        b_sh[t] = bb;
        cA = a; cB = bb;
        sA[t] = a; sB[t] = bb;
    }
    __syncthreads();

    // inclusive pair scan: u_i = B_i + A_i * Up_c
#pragma unroll
    for (int off = 1; off < RR; off <<= 1) {
        float va = 1.f, vb = 0.f;
        if (t < RR && t >= off) { va = sA[t - off]; vb = sB[t - off]; }
        __syncthreads();
        if (t < RR) {
            cB = fmaf(vb, cA, cB);
            cA = va * cA;
            sA[t] = cA; sB[t] = cB;
        }
        __syncthreads();
    }
    if (t < RR) inv_sh[t] = 1.0f / fmaf(cA, Up_c, cB);
    __syncthreads();

    // --- stream: w recurrence over 64 rows, double-buffered ---
    for (int ib = 0; ib < RR; ib += 8) {
        float nxt[8];
#pragma unroll
        for (int j = 0; j < 8; j++)
            nxt[j] = (ib + 8 < RR) ? Vb[(size_t)(ib + 8 + j) * DD] : 0.f;
#pragma unroll
        for (int j = 0; j < 8; j++) {
            int i = ib + j;
            w = fmaf(w, a_sh[i], b_sh[i] * cur[j]);
            __stcs(&Ob[(size_t)i * DD], w * inv_sh[i]);   // write-once: stream
        }
#pragma unroll
        for (int j = 0; j < 8; j++) cur[j] = nxt[j];
    }
}

// ============================================================
extern "C" void kernel_launch(void* const* d_in, const int* in_sizes, int n_in,
                              void* d_out, int out_size) {
    const float* K = (const float*)d_in[0];
    const float* V = (const float*)d_in[1];
    const float* q = (const float*)d_in[2];
    float* out = (float*)d_out;

    k_pass1<<<CC, 256>>>(K, V, q);

    cudaLaunchAttribute attr[1];
    attr[0].id = cudaLaunchAttributeProgrammaticStreamSerialization;
    attr[0].val.programmaticStreamSerializationAllowed = 1;

    {
        cudaLaunchConfig_t cfg = {};
        cfg.gridDim = dim3(NSEG);
        cfg.blockDim = dim3(256);
        cfg.dynamicSmemBytes = 0;
        cfg.stream = 0;
        cfg.attrs = attr;
        cfg.numAttrs = 1;
        cudaLaunchKernelEx(&cfg, k_mid);
    }
    {
        cudaLaunchConfig_t cfg = {};
        cfg.gridDim = dim3(CC);
        cfg.blockDim = dim3(256);
        cfg.dynamicSmemBytes = 0;
        cfg.stream = 0;
        cfg.attrs = attr;
        cfg.numAttrs = 1;
        cudaLaunchKernelEx(&cfg, k_pass2, (const float*)V, (float*)out);
    }
}

// round 14
// speedup vs baseline: 1.1291x; 1.0428x over previous
#include <cuda_runtime.h>
#include <cuda_bf16.h>
#include <cstdint>

#define LL 65536
#define DD 256
#define CC 1024     // number of chunks
#define RR 64       // rows per chunk
#define NSEG 32     // segments
#define SEGC 32     // chunks per segment (CC / NSEG)

#define NEG_INF __int_as_float(0xff800000)

// ---- scratch (device globals) ----
__device__ float g_s[LL];            // s[i] = K[i]·q
__device__ float g_M[CC], g_U[CC];   // per-chunk aggregates (U ref M)
__device__ float g_W[CC * DD];       // per-chunk vector aggregate (ref M_c)
__device__ float g_Mp[CC], g_Up[CC]; // exclusive prefix (Up ref Mp)
__device__ float g_Wp[CC * DD];      // segment-local exclusive W prefix (ref Mp_c)
__device__ float g_seg[NSEG * DD];   // segment aggregates (ref Mp[(b+1)*SEGC])

__device__ __forceinline__ void pdl_trigger() {
    asm volatile("griddepcontrol.launch_dependents;");
}
__device__ __forceinline__ void pdl_wait() {
    asm volatile("griddepcontrol.wait;");
}

// ============================================================
// Pass 1: warp-local K-dot AND V-accumulate (no block barrier
// between the two DRAM streams); 72 expf/block total.
// Warp w owns rows 8w..8w+7; lane covers dims 4l..4l+3, 128+4l..
// ============================================================
__global__ __launch_bounds__(256, 8) void k_pass1(const float* __restrict__ K,
                                                  const float* __restrict__ V,
                                                  const float* __restrict__ q) {
    __shared__ __align__(16) float wp[8][DD];   // 8KB warp-partial W (ref mw)
    __shared__ float s_sh[RR];
    __shared__ float e_sh[RR];
    __shared__ float mw_sh[8], Uw_sh[8], sc_sh[8];

    const int c = blockIdx.x;
    const int t = threadIdx.x;
    const int lane = t & 31;
    const int wid = t >> 5;

    const float4* q4g = reinterpret_cast<const float4*>(q);
    const float4 qa = q4g[lane];
    const float4 qb = q4g[32 + lane];

    const float4* K4 = reinterpret_cast<const float4*>(K) + (size_t)(c * RR + wid * 8) * 64;
    const float4* V4 = reinterpret_cast<const float4*>(V) + (size_t)(c * RR + wid * 8) * 64;

    // --- 8 K-row dots (warp-local), running warp max ---
    float mw = NEG_INF;
#pragma unroll
    for (int k = 0; k < 8; k++) {
        float4 ka = __ldcs(&K4[k * 64 + lane]);        // K read-once: evict-first
        float4 kb = __ldcs(&K4[k * 64 + 32 + lane]);
        float p = ka.x * qa.x + ka.y * qa.y + ka.z * qa.z + ka.w * qa.w
                + kb.x * qb.x + kb.y * qb.y + kb.z * qb.z + kb.w * qb.w;
#pragma unroll
        for (int o = 16; o; o >>= 1) p += __shfl_xor_sync(0xffffffffu, p, o);
        if (lane == k) s_sh[wid * 8 + k] = p;          // stash row dot
        mw = fmaxf(mw, p);                             // identical on all lanes
    }
    __syncwarp();

    // --- e: ONE expf per row (lanes 0..7 only) ---
    if (lane < 8) e_sh[wid * 8 + lane] = __expf(s_sh[wid * 8 + lane] - mw);
    __syncwarp();

    // --- V accumulate (warp-local, starts right after) ---
    float4 aa = make_float4(0.f, 0.f, 0.f, 0.f);
    float4 ab = make_float4(0.f, 0.f, 0.f, 0.f);
#pragma unroll
    for (int k = 0; k < 8; k++) {
        float4 va = V4[k * 64 + lane];
        float4 vb = V4[k * 64 + 32 + lane];
        float e = e_sh[wid * 8 + k];
        aa.x = fmaf(e, va.x, aa.x); aa.y = fmaf(e, va.y, aa.y);
        aa.z = fmaf(e, va.z, aa.z); aa.w = fmaf(e, va.w, aa.w);
        ab.x = fmaf(e, vb.x, ab.x); ab.y = fmaf(e, vb.y, ab.y);
        ab.z = fmaf(e, vb.z, ab.z); ab.w = fmaf(e, vb.w, ab.w);
    }
    {
        float4* wp4 = reinterpret_cast<float4*>(wp[wid]);
        wp4[lane] = aa;
        wp4[32 + lane] = ab;
    }
    if (lane == 0) {
        float Uw = 0.f;
#pragma unroll
        for (int k = 0; k < 8; k++) Uw += e_sh[wid * 8 + k];
        Uw_sh[wid] = Uw;
        mw_sh[wid] = mw;
    }
    __syncthreads();

    // --- combine 8 warp partials ---
    float M = mw_sh[0];
#pragma unroll
    for (int w = 1; w < 8; w++) M = fmaxf(M, mw_sh[w]);
    if (t < 8) sc_sh[t] = __expf(mw_sh[t] - M);        // 8 expf total
    __syncthreads();

    float W = 0.f;
#pragma unroll
    for (int w = 0; w < 8; w++) W = fmaf(sc_sh[w], wp[w][t], W);
    g_W[(size_t)c * DD + t] = W;

    if (t == 0) {
        float U = 0.f;
#pragma unroll
        for (int w = 0; w < 8; w++) U = fmaf(sc_sh[w], Uw_sh[w], U);
        g_M[c] = M;
        g_U[c] = U;
    }
    if (t < RR) g_s[c * RR + t] = s_sh[t];

    pdl_trigger();
}

// ============================================================
// Mid kernel: NSEG blocks. All-parallel scalar scans; block b
// does the register-resident segment W-scan for its chunks.
// ============================================================
__global__ __launch_bounds__(256) void k_mid() {
    __shared__ float Pm[CC];
    __shared__ float alsh[CC];
    __shared__ float gash[CC];
    __shared__ float As[CC];
    __shared__ float Bs[CC];

    const int b = blockIdx.x;
    const int t = threadIdx.x;

    pdl_wait();      // need pass1's g_M/g_U/g_W/g_s

    float mv[4];
#pragma unroll
    for (int r = 0; r < 4; r++) {
        mv[r] = g_M[t + r * 256];
        Pm[t + r * 256] = mv[r];
    }
    __syncthreads();

    float cm[4];
#pragma unroll
    for (int r = 0; r < 4; r++) cm[r] = mv[r];
    for (int off = 1; off < CC; off <<= 1) {
        float v[4];
#pragma unroll
        for (int r = 0; r < 4; r++) {
            int i = t + r * 256;
            v[r] = (i >= off) ? Pm[i - off] : NEG_INF;
        }
        __syncthreads();
#pragma unroll
        for (int r = 0; r < 4; r++) {
            cm[r] = fmaxf(cm[r], v[r]);
            Pm[t + r * 256] = cm[r];
        }
        __syncthreads();
    }

    float ca[4], cb[4];
#pragma unroll
    for (int r = 0; r < 4; r++) {
        int i = t + r * 256;
        float Minc = Pm[i];
        float Mp = (i == 0) ? NEG_INF : Pm[i - 1];
        float a = (i == 0) ? 0.f : __expf(Mp - Minc);
        float g = __expf(mv[r] - Minc);
        alsh[i] = a;
        gash[i] = g;
        ca[r] = a;
        cb[r] = g_U[i] * g;
        As[i] = ca[r];
        Bs[i] = cb[r];
        if (b == 0) g_Mp[i] = Mp;
    }
    __syncthreads();

    for (int off = 1; off < CC; off <<= 1) {
        float va[4], vb[4];
#pragma unroll
        for (int r = 0; r < 4; r++) {
            int i = t + r * 256;
            if (i >= off) { va[r] = As[i - off]; vb[r] = Bs[i - off]; }
            else          { va[r] = 1.f;         vb[r] = 0.f; }
        }
        __syncthreads();
#pragma unroll
        for (int r = 0; r < 4; r++) {
            int i = t + r * 256;
            cb[r] = fmaf(vb[r], ca[r], cb[r]);
            ca[r] = va[r] * ca[r];
            As[i] = ca[r];
            Bs[i] = cb[r];
        }
        __syncthreads();
    }

    if (b == 0) {
#pragma unroll
        for (int r = 0; r < 4; r++) {
            int i = t + r * 256;
            g_Up[i] = (i == 0) ? 0.f : Bs[i - 1];   // exclusive, ref Mp_i
        }
    }

    const int j0 = b * SEGC;
    const float* Wsrc = g_W + (size_t)j0 * DD + t;
    float* Wdst = g_Wp + (size_t)j0 * DD + t;

    float wc[SEGC];
#pragma unroll
    for (int j = 0; j < SEGC; j++) wc[j] = Wsrc[(size_t)j * DD];

    float w = 0.f;
#pragma unroll
    for (int j = 0; j < SEGC; j++) {
        Wdst[(size_t)j * DD] = w;              // exclusive within segment, ref Mp_c
        w = fmaf(w, alsh[j0 + j], wc[j] * gash[j0 + j]);
    }
    g_seg[b * DD + t] = w;                     // ref Mp[(b+1)*SEGC]

    pdl_trigger();
}

// ============================================================
// Pass 2: per-row recurrence via warp-shfl scans (3 syncthreads),
// stream V -> out. V cur[8] loaded BEFORE the PDL wait.
// ============================================================
__global__ __launch_bounds__(256, 8) void k_pass2(const float* __restrict__ V,
                                                  float* __restrict__ out) {
    __shared__ float a_sh[RR], b_sh[RR], inv_sh[RR];
    __shared__ float fac_sh[NSEG];
    __shared__ float w0max, w0A, w0B;

    const int c = (CC - 1) - blockIdx.x;
    const int t = threadIdx.x;
    const int lane = t & 31;

    const float* Vb = V + (size_t)c * RR * DD + t;
    float* Ob = out + (size_t)c * RR * DD + t;

    // --- V prefetch BEFORE wait: input data, independent of mid ---
    float cur[8];
#pragma unroll
    for (int j = 0; j < 8; j++) cur[j] = Vb[(size_t)j * DD];

    pdl_wait();      // need mid's g_Mp/g_Up/g_Wp/g_seg (and pass1's g_s)

    const float Mp_c = g_Mp[c];
    const float Up_c = g_Up[c];
    const int seg = c / SEGC;

    // telescoped carry factors
    if (t < seg) fac_sh[t] = __expf(g_Mp[(t + 1) * SEGC] - Mp_c);

    // --- warp-level inclusive max scan over s (threads 0..63) ---
    float sv = 0.f, m = NEG_INF;
    if (t < RR) {
        sv = g_s[c * RR + t];
        m = sv;
#pragma unroll
        for (int off = 1; off < 32; off <<= 1) {
            float v = __shfl_up_sync(0xffffffffu, m, off);
            if (lane >= off) m = fmaxf(m, v);
        }
        if (t == 31) w0max = m;
    }
    __syncthreads();   // (1): w0max + fac_sh visible

    // seed: w = Wp_c + sum_sb g_seg[sb][t] * fac[sb]  (overlaps scan math)
    float w = g_Wp[(size_t)c * DD + t];
#pragma unroll 4
    for (int sb = 0; sb < seg; sb++)
        w = fmaf(__ldcg(&g_seg[sb * DD + t]), fac_sh[sb], w);

    float cA = 1.f, cB = 0.f;
    if (t < RR) {
        if (t >= 32) m = fmaxf(m, w0max);
        float mprev = __shfl_up_sync(0xffffffffu, m, 1);
        if (t == 32) mprev = w0max;
        float mi = fmaxf(m, Mp_c);
        float mp = (t == 0) ? Mp_c : fmaxf(mprev, Mp_c);
        float a = __expf(mp - mi);             // exp(-inf - finite) = 0 : safe
        float bb = __expf(sv - mi);
        a_sh[t] = a;
        b_sh[t] = bb;
        // warp-level inclusive pair scan for u
        cA = a; cB = bb;
#pragma unroll
        for (int off = 1; off < 32; off <<= 1) {
            float va = __shfl_up_sync(0xffffffffu, cA, off);
            float vb = __shfl_up_sync(0xffffffffu, cB, off);
            if (lane >= off) { cB = fmaf(vb, cA, cB); cA = va * cA; }
        }
        if (t == 31) { w0A = cA; w0B = cB; }
    }
    __syncthreads();   // (2): w0A/w0B visible

    if (t < RR) {
        if (t >= 32) { cB = fmaf(w0B, cA, cB); cA = w0A * cA; }
        inv_sh[t] = 1.0f / fmaf(cA, Up_c, cB);
    }
    __syncthreads();   // (3): a_sh/b_sh/inv_sh ready

    // --- stream: w recurrence over 64 rows, double-buffered ---
    for (int ib = 0; ib < RR; ib += 8) {
        float nxt[8];
#pragma unroll
        for (int j = 0; j < 8; j++)
            nxt[j] = (ib + 8 < RR) ? Vb[(size_t)(ib + 8 + j) * DD] : 0.f;
#pragma unroll
        for (int j = 0; j < 8; j++) {
            int i = ib + j;
            w = fmaf(w, a_sh[i], b_sh[i] * cur[j]);
            __stcs(&Ob[(size_t)i * DD], w * inv_sh[i]);   // write-once: stream
        }
#pragma unroll
        for (int j = 0; j < 8; j++) cur[j] = nxt[j];
    }
}

// ============================================================
extern "C" void kernel_launch(void* const* d_in, const int* in_sizes, int n_in,
                              void* d_out, int out_size) {
    const float* K = (const float*)d_in[0];
    const float* V = (const float*)d_in[1];
    const float* q = (const float*)d_in[2];
    float* out = (float*)d_out;

    k_pass1<<<CC, 256>>>(K, V, q);

    cudaLaunchAttribute attr[1];
    attr[0].id = cudaLaunchAttributeProgrammaticStreamSerialization;
    attr[0].val.programmaticStreamSerializationAllowed = 1;

    {
        cudaLaunchConfig_t cfg = {};
        cfg.gridDim = dim3(NSEG);
        cfg.blockDim = dim3(256);
        cfg.dynamicSmemBytes = 0;
        cfg.stream = 0;
        cfg.attrs = attr;
        cfg.numAttrs = 1;
        cudaLaunchKernelEx(&cfg, k_mid);
    }
    {
        cudaLaunchConfig_t cfg = {};
        cfg.gridDim = dim3(CC);
        cfg.blockDim = dim3(256);
        cfg.dynamicSmemBytes = 0;
        cfg.stream = 0;
        cfg.attrs = attr;
        cfg.numAttrs = 1;
        cudaLaunchKernelEx(&cfg, k_pass2, (const float*)V, (float*)out);
    }
}

// round 15
// speedup vs baseline: 1.1344x; 1.0047x over previous
#include <cuda_runtime.h>
#include <cuda_bf16.h>
#include <cstdint>

#define LL 65536
#define DD 256
#define CC 1024     // number of chunks
#define RR 64       // rows per chunk
#define NSEG 32     // segments
#define SEGC 32     // chunks per segment (CC / NSEG)

#define NEG_INF __int_as_float(0xff800000)

// ---- scratch (device globals) ----
__device__ float g_s[LL];            // s[i] = K[i]·q
__device__ float g_M[CC], g_U[CC];   // per-chunk aggregates (U ref M)
__device__ float g_W[CC * DD];       // per-chunk vector aggregate (ref M_c)
__device__ float g_Mp[CC], g_Up[CC]; // exclusive prefix (Up ref Mp)
__device__ float g_Wp[CC * DD];      // segment-local exclusive W prefix (ref Mp_c)
__device__ float g_seg[NSEG * DD];   // segment aggregates (ref Mp[(b+1)*SEGC])

__device__ __forceinline__ void pdl_trigger() {
    asm volatile("griddepcontrol.launch_dependents;");
}
__device__ __forceinline__ void pdl_wait() {
    asm volatile("griddepcontrol.wait;");
}

// ============================================================
// Pass 1 (R13 variant — best measured: 24.86us):
// s = K·q ; per-chunk (M, U, W) reduction; V register prefetch
// across the reduction bubble; warp-0-only reduction (64 expf).
// ============================================================
__global__ __launch_bounds__(256, 8) void k_pass1(const float* __restrict__ K,
                                                  const float* __restrict__ V,
                                                  const float* __restrict__ q) {
    __shared__ __align__(16) float q_sh[DD];
    __shared__ __align__(16) float wpart[4][DD];
    __shared__ float s_sh[RR];
    __shared__ float e_sh[RR];

    const int c = blockIdx.x;
    const int t = threadIdx.x;
    const int lane = t & 31;
    const int wid = t >> 5;

    q_sh[t] = q[t];
    __syncthreads();

    const float4* q4 = reinterpret_cast<const float4*>(q_sh);
    const float4* K4 = reinterpret_cast<const float4*>(K) + (size_t)c * RR * 64;

    // --- K-dot: 8 warps x 8 rows, one warp per row ---
    float4 qa = q4[lane], qb = q4[32 + lane];
#pragma unroll
    for (int k = 0; k < RR / 8; k++) {
        int r = wid * (RR / 8) + k;
        float4 ka = __ldcs(&K4[r * 64 + lane]);        // K read-once: evict-first
        float4 kb = __ldcs(&K4[r * 64 + 32 + lane]);
        float p = ka.x * qa.x + ka.y * qa.y + ka.z * qa.z + ka.w * qa.w
                + kb.x * qb.x + kb.y * qb.y + kb.z * qb.z + kb.w * qb.w;
#pragma unroll
        for (int o = 16; o; o >>= 1) p += __shfl_xor_sync(0xffffffffu, p, o);
        if (lane == 0) s_sh[r] = p;
    }
    __syncthreads();

    // --- prefetch first 4 V rows per thread (independent of reduction) ---
    const int grp = t >> 6;
    const int j = t & 63;
    const float4* V4 = reinterpret_cast<const float4*>(V) + (size_t)c * RR * 64;
    float4 v0 = V4[(grp +  0) * 64 + j];
    float4 v1 = V4[(grp +  4) * 64 + j];
    float4 v2 = V4[(grp +  8) * 64 + j];
    float4 v3 = V4[(grp + 12) * 64 + j];

    // --- warp 0: M, e, U (64 expf total) ---
    if (wid == 0) {
        float s0 = s_sh[lane], s1 = s_sh[32 + lane];
        float m = fmaxf(s0, s1);
#pragma unroll
        for (int o = 16; o; o >>= 1) m = fmaxf(m, __shfl_xor_sync(0xffffffffu, m, o));
        float e0 = __expf(s0 - m), e1 = __expf(s1 - m);
        e_sh[lane] = e0; e_sh[32 + lane] = e1;
        float u = e0 + e1;
#pragma unroll
        for (int o = 16; o; o >>= 1) u += __shfl_xor_sync(0xffffffffu, u, o);
        if (lane == 0) { g_M[c] = m; g_U[c] = u; }
    }
    if (t < RR) g_s[c * RR + t] = s_sh[t];
    __syncthreads();

    // --- V accumulate: consume prefetched batch, then stream the rest ---
    float4 acc;
    {
        float e0 = e_sh[grp], e1 = e_sh[grp + 4], e2 = e_sh[grp + 8], e3 = e_sh[grp + 12];
        acc.x = e0 * v0.x + e1 * v1.x + e2 * v2.x + e3 * v3.x;
        acc.y = e0 * v0.y + e1 * v1.y + e2 * v2.y + e3 * v3.y;
        acc.z = e0 * v0.z + e1 * v1.z + e2 * v2.z + e3 * v3.z;
        acc.w = e0 * v0.w + e1 * v1.w + e2 * v2.w + e3 * v3.w;
    }
#pragma unroll
    for (int i = grp + 16; i < RR; i += 4) {
        float e = e_sh[i];
        float4 v = V4[i * 64 + j];
        acc.x = fmaf(e, v.x, acc.x); acc.y = fmaf(e, v.y, acc.y);
        acc.z = fmaf(e, v.z, acc.z); acc.w = fmaf(e, v.w, acc.w);
    }
    reinterpret_cast<float4*>(wpart[grp])[j] = acc;
    __syncthreads();
    g_W[(size_t)c * DD + t] = wpart[0][t] + wpart[1][t] + wpart[2][t] + wpart[3][t];

    pdl_trigger();
}

// ============================================================
// Mid kernel: NSEG blocks. All-parallel scalar scans; block b
// does the register-resident segment W-scan for its chunks.
// ============================================================
__global__ __launch_bounds__(256) void k_mid() {
    __shared__ float Pm[CC];
    __shared__ float alsh[CC];
    __shared__ float gash[CC];
    __shared__ float As[CC];
    __shared__ float Bs[CC];

    const int b = blockIdx.x;
    const int t = threadIdx.x;

    pdl_wait();      // need pass1's g_M/g_U/g_W/g_s

    float mv[4];
#pragma unroll
    for (int r = 0; r < 4; r++) {
        mv[r] = g_M[t + r * 256];
        Pm[t + r * 256] = mv[r];
    }
    __syncthreads();

    float cm[4];
#pragma unroll
    for (int r = 0; r < 4; r++) cm[r] = mv[r];
    for (int off = 1; off < CC; off <<= 1) {
        float v[4];
#pragma unroll
        for (int r = 0; r < 4; r++) {
            int i = t + r * 256;
            v[r] = (i >= off) ? Pm[i - off] : NEG_INF;
        }
        __syncthreads();
#pragma unroll
        for (int r = 0; r < 4; r++) {
            cm[r] = fmaxf(cm[r], v[r]);
            Pm[t + r * 256] = cm[r];
        }
        __syncthreads();
    }

    float ca[4], cb[4];
#pragma unroll
    for (int r = 0; r < 4; r++) {
        int i = t + r * 256;
        float Minc = Pm[i];
        float Mp = (i == 0) ? NEG_INF : Pm[i - 1];
        float a = (i == 0) ? 0.f : __expf(Mp - Minc);
        float g = __expf(mv[r] - Minc);
        alsh[i] = a;
        gash[i] = g;
        ca[r] = a;
        cb[r] = g_U[i] * g;
        As[i] = ca[r];
        Bs[i] = cb[r];
        if (b == 0) g_Mp[i] = Mp;
    }
    __syncthreads();

    for (int off = 1; off < CC; off <<= 1) {
        float va[4], vb[4];
#pragma unroll
        for (int r = 0; r < 4; r++) {
            int i = t + r * 256;
            if (i >= off) { va[r] = As[i - off]; vb[r] = Bs[i - off]; }
            else          { va[r] = 1.f;         vb[r] = 0.f; }
        }
        __syncthreads();
#pragma unroll
        for (int r = 0; r < 4; r++) {
            int i = t + r * 256;
            cb[r] = fmaf(vb[r], ca[r], cb[r]);
            ca[r] = va[r] * ca[r];
            As[i] = ca[r];
            Bs[i] = cb[r];
        }
        __syncthreads();
    }

    if (b == 0) {
#pragma unroll
        for (int r = 0; r < 4; r++) {
            int i = t + r * 256;
            g_Up[i] = (i == 0) ? 0.f : Bs[i - 1];   // exclusive, ref Mp_i
        }
    }

    const int j0 = b * SEGC;
    const float* Wsrc = g_W + (size_t)j0 * DD + t;
    float* Wdst = g_Wp + (size_t)j0 * DD + t;

    float wc[SEGC];
#pragma unroll
    for (int j = 0; j < SEGC; j++) wc[j] = Wsrc[(size_t)j * DD];

    float w = 0.f;
#pragma unroll
    for (int j = 0; j < SEGC; j++) {
        Wdst[(size_t)j * DD] = w;              // exclusive within segment, ref Mp_c
        w = fmaf(w, alsh[j0 + j], wc[j] * gash[j0 + j]);
    }
    g_seg[b * DD + t] = w;                     // ref Mp[(b+1)*SEGC]

    pdl_trigger();
}

// ============================================================
// Pass 2 (R14 variant — warp-shfl scans, 3 syncthreads):
// per-row recurrence, stream V -> out. V cur[8] pre-wait.
// ============================================================
__global__ __launch_bounds__(256, 8) void k_pass2(const float* __restrict__ V,
                                                  float* __restrict__ out) {
    __shared__ float a_sh[RR], b_sh[RR], inv_sh[RR];
    __shared__ float fac_sh[NSEG];
    __shared__ float w0max, w0A, w0B;

    const int c = (CC - 1) - blockIdx.x;
    const int t = threadIdx.x;
    const int lane = t & 31;

    const float* Vb = V + (size_t)c * RR * DD + t;
    float* Ob = out + (size_t)c * RR * DD + t;

    // --- V prefetch BEFORE wait: input data, independent of mid ---
    float cur[8];
#pragma unroll
    for (int j = 0; j < 8; j++) cur[j] = Vb[(size_t)j * DD];

    pdl_wait();      // need mid's g_Mp/g_Up/g_Wp/g_seg (and pass1's g_s)

    const float Mp_c = g_Mp[c];
    const float Up_c = g_Up[c];
    const int seg = c / SEGC;

    // telescoped carry factors
    if (t < seg) fac_sh[t] = __expf(g_Mp[(t + 1) * SEGC] - Mp_c);

    // --- warp-level inclusive max scan over s (threads 0..63) ---
    float sv = 0.f, m = NEG_INF;
    if (t < RR) {
        sv = g_s[c * RR + t];
        m = sv;
#pragma unroll
        for (int off = 1; off < 32; off <<= 1) {
            float v = __shfl_up_sync(0xffffffffu, m, off);
            if (lane >= off) m = fmaxf(m, v);
        }
        if (t == 31) w0max = m;
    }
    __syncthreads();   // (1): w0max + fac_sh visible

    // seed: w = Wp_c + sum_sb g_seg[sb][t] * fac[sb]  (overlaps scan math)
    float w = g_Wp[(size_t)c * DD + t];
#pragma unroll 4
    for (int sb = 0; sb < seg; sb++)
        w = fmaf(__ldcg(&g_seg[sb * DD + t]), fac_sh[sb], w);

    float cA = 1.f, cB = 0.f;
    if (t < RR) {
        if (t >= 32) m = fmaxf(m, w0max);
        float mprev = __shfl_up_sync(0xffffffffu, m, 1);
        if (t == 32) mprev = w0max;
        float mi = fmaxf(m, Mp_c);
        float mp = (t == 0) ? Mp_c : fmaxf(mprev, Mp_c);
        float a = __expf(mp - mi);             // exp(-inf - finite) = 0 : safe
        float bb = __expf(sv - mi);
        a_sh[t] = a;
        b_sh[t] = bb;
        // warp-level inclusive pair scan for u
        cA = a; cB = bb;
#pragma unroll
        for (int off = 1; off < 32; off <<= 1) {
            float va = __shfl_up_sync(0xffffffffu, cA, off);
            float vb = __shfl_up_sync(0xffffffffu, cB, off);
            if (lane >= off) { cB = fmaf(vb, cA, cB); cA = va * cA; }
        }
        if (t == 31) { w0A = cA; w0B = cB; }
    }
    __syncthreads();   // (2): w0A/w0B visible

    if (t < RR) {
        if (t >= 32) { cB = fmaf(w0B, cA, cB); cA = w0A * cA; }
        inv_sh[t] = 1.0f / fmaf(cA, Up_c, cB);
    }
    __syncthreads();   // (3): a_sh/b_sh/inv_sh ready

    // --- stream: w recurrence over 64 rows, double-buffered ---
    for (int ib = 0; ib < RR; ib += 8) {
        float nxt[8];
#pragma unroll
        for (int j = 0; j < 8; j++)
            nxt[j] = (ib + 8 < RR) ? Vb[(size_t)(ib + 8 + j) * DD] : 0.f;
#pragma unroll
        for (int j = 0; j < 8; j++) {
            int i = ib + j;
            w = fmaf(w, a_sh[i], b_sh[i] * cur[j]);
            __stcs(&Ob[(size_t)i * DD], w * inv_sh[i]);   // write-once: stream
        }
#pragma unroll
        for (int j = 0; j < 8; j++) cur[j] = nxt[j];
    }
}

// ============================================================
extern "C" void kernel_launch(void* const* d_in, const int* in_sizes, int n_in,
                              void* d_out, int out_size) {
    const float* K = (const float*)d_in[0];
    const float* V = (const float*)d_in[1];
    const float* q = (const float*)d_in[2];
    float* out = (float*)d_out;

    k_pass1<<<CC, 256>>>(K, V, q);

    cudaLaunchAttribute attr[1];
    attr[0].id = cudaLaunchAttributeProgrammaticStreamSerialization;
    attr[0].val.programmaticStreamSerializationAllowed = 1;

    {
        cudaLaunchConfig_t cfg = {};
        cfg.gridDim = dim3(NSEG);
        cfg.blockDim = dim3(256);
        cfg.dynamicSmemBytes = 0;
        cfg.stream = 0;
        cfg.attrs = attr;
        cfg.numAttrs = 1;
        cudaLaunchKernelEx(&cfg, k_mid);
    }
    {
        cudaLaunchConfig_t cfg = {};
        cfg.gridDim = dim3(CC);
        cfg.blockDim = dim3(256);
        cfg.dynamicSmemBytes = 0;
        cfg.stream = 0;
        cfg.attrs = attr;
        cfg.numAttrs = 1;
        cudaLaunchKernelEx(&cfg, k_pass2, (const float*)V, (float*)out);
    }
}